// round 4
// baseline (speedup 1.0000x reference)
#include <cuda_runtime.h>
#include <math.h>

#define BB   4
#define NN   500
#define KNN  50
#define DD   2048
#define H0   28
#define HW0  (H0*H0)
#define C0   512
#define H1   14
#define HW1  (H1*H1)
#define C1   1024
#define IMG  224
#define KS   33
#define RR   16

// scratch (static device globals — no runtime allocation)
__device__ float g_dist[BB * NN];
__device__ int   g_idx[BB * KNN];
__device__ float g_m0[BB * HW0];
__device__ float g_m1[BB * HW1];
__device__ float g_mask[BB * IMG * IMG];
__device__ float g_tmp[BB * IMG * IMG];
__device__ float g_kw[KS];

// ---------------------------------------------------------------------------
// 1) pairwise distances q[4,2048] vs bank[500,2048] -> g_dist[4*500]
//    one block per n, one warp per b
// ---------------------------------------------------------------------------
__global__ void dist_kernel(const float* __restrict__ q,
                            const float* __restrict__ bank) {
    int n    = blockIdx.x;
    int warp = threadIdx.x >> 5;
    int lane = threadIdx.x & 31;
    int b    = warp;

    const float4* qb = (const float4*)(q    + (size_t)b * DD);
    const float4* bk = (const float4*)(bank + (size_t)n * DD);

    float acc = 0.f;
#pragma unroll
    for (int j = 0; j < DD / 128; ++j) {
        float4 a = qb[lane + 32 * j];
        float4 c = bk[lane + 32 * j];
        float dx = a.x - c.x, dy = a.y - c.y, dz = a.z - c.z, dw = a.w - c.w;
        acc = fmaf(dx, dx, acc);
        acc = fmaf(dy, dy, acc);
        acc = fmaf(dz, dz, acc);
        acc = fmaf(dw, dw, acc);
    }
#pragma unroll
    for (int o = 16; o; o >>= 1) acc += __shfl_xor_sync(0xFFFFFFFFu, acc, o);
    if (lane == 0) g_dist[b * NN + n] = sqrtf(acc);
}

// ---------------------------------------------------------------------------
// 2) top-K smallest per b -> g_idx, score (mean of K smallest) -> out[b]
//    one block per b; ties break toward lower index (jax.lax.top_k behavior)
// ---------------------------------------------------------------------------
__global__ void topk_kernel(float* __restrict__ out_score) {
    int b = blockIdx.x;
    __shared__ float sv[NN];
    __shared__ float rv[256];
    __shared__ int   ri[256];
    int tid = threadIdx.x;

    for (int i = tid; i < NN; i += 256) sv[i] = g_dist[b * NN + i];
    __syncthreads();

    __shared__ float ssum;
    if (tid == 0) ssum = 0.f;

    for (int k = 0; k < KNN; ++k) {
        float best = 3.4e38f;
        int   bi   = 0x7FFFFFFF;
        for (int i = tid; i < NN; i += 256) {
            float v = sv[i];
            if (v < best || (v == best && i < bi)) { best = v; bi = i; }
        }
        rv[tid] = best; ri[tid] = bi;
        __syncthreads();
        for (int s = 128; s; s >>= 1) {
            if (tid < s) {
                float v2 = rv[tid + s]; int i2 = ri[tid + s];
                if (v2 < rv[tid] || (v2 == rv[tid] && i2 < ri[tid])) {
                    rv[tid] = v2; ri[tid] = i2;
                }
            }
            __syncthreads();
        }
        if (tid == 0) {
            g_idx[b * KNN + k] = ri[0];
            sv[ri[0]] = 3.4e38f;
            ssum += rv[0];
        }
        __syncthreads();
    }
    if (tid == 0) out_score[b] = ssum / (float)KNN;
}

// ---------------------------------------------------------------------------
// 3) per-pixel min distance over K gathered neighbors
//    one block per (pos, b); 8 warps; warp w handles k = w, w+8, ...
//    x row cached in registers per lane; fully unrolled float4 loads for MLP
// ---------------------------------------------------------------------------
template <int HW, int C>
__global__ void __launch_bounds__(256) mindist_kernel(
        const float* __restrict__ x, const float* __restrict__ f) {
    int pos  = blockIdx.x;
    int b    = blockIdx.y;
    int warp = threadIdx.x >> 5;
    int lane = threadIdx.x & 31;
    constexpr int J = C / 128;

    const float4* xr = (const float4*)(x + ((size_t)b * HW + pos) * C);
    float4 xv[J];
#pragma unroll
    for (int j = 0; j < J; ++j) xv[j] = xr[lane + 32 * j];

    float best = 3.4e38f;
    for (int k = warp; k < KNN; k += 8) {
        int n = g_idx[b * KNN + k];
        const float4* fr = (const float4*)(f + ((size_t)n * HW + pos) * C);
        float acc = 0.f;
#pragma unroll
        for (int j = 0; j < J; ++j) {
            float4 c = fr[lane + 32 * j];
            float dx = xv[j].x - c.x, dy = xv[j].y - c.y;
            float dz = xv[j].z - c.z, dw = xv[j].w - c.w;
            acc = fmaf(dx, dx, acc);
            acc = fmaf(dy, dy, acc);
            acc = fmaf(dz, dz, acc);
            acc = fmaf(dw, dw, acc);
        }
#pragma unroll
        for (int o = 16; o; o >>= 1) acc += __shfl_xor_sync(0xFFFFFFFFu, acc, o);
        best = fminf(best, acc);
    }

    __shared__ float sb[8];
    if (lane == 0) sb[warp] = best;
    __syncthreads();
    if (threadIdx.x == 0) {
        float v = sb[0];
#pragma unroll
        for (int i = 1; i < 8; ++i) v = fminf(v, sb[i]);
        float* m = (HW == HW0) ? g_m0 : g_m1;
        m[b * HW + pos] = sqrtf(v);
    }
}

// ---------------------------------------------------------------------------
// 4) bilinear upsample (half-pixel centers, edge clamp) of both maps + average
// ---------------------------------------------------------------------------
__device__ __forceinline__ float bilerp(const float* __restrict__ img, int S,
                                        float cx, float cy) {
    float fx = floorf(cx), fy = floorf(cy);
    int x0 = (int)fx, y0 = (int)fy;
    float wx = cx - fx, wy = cy - fy;
    int x1 = min(x0 + 1, S - 1), y1 = min(y0 + 1, S - 1);
    x0 = max(x0, 0); y0 = max(y0, 0);
    float v00 = img[y0 * S + x0], v01 = img[y0 * S + x1];
    float v10 = img[y1 * S + x0], v11 = img[y1 * S + x1];
    return (1.f - wy) * ((1.f - wx) * v00 + wx * v01)
         + wy * ((1.f - wx) * v10 + wx * v11);
}

__global__ void resize_avg_kernel() {
    int idx = blockIdx.x * blockDim.x + threadIdx.x;
    if (idx >= BB * IMG * IMG) return;
    int x = idx % IMG;
    int y = (idx / IMG) % IMG;
    int b = idx / (IMG * IMG);

    float cx0 = (x + 0.5f) * ((float)H0 / IMG) - 0.5f;
    float cy0 = (y + 0.5f) * ((float)H0 / IMG) - 0.5f;
    float cx1 = (x + 0.5f) * ((float)H1 / IMG) - 0.5f;
    float cy1 = (y + 0.5f) * ((float)H1 / IMG) - 0.5f;

    float m0 = bilerp(g_m0 + b * HW0, H0, cx0, cy0);
    float m1 = bilerp(g_m1 + b * HW1, H1, cx1, cy1);
    g_mask[idx] = 0.5f * (m0 + m1);
}

// ---------------------------------------------------------------------------
// 5) gaussian weights (sigma=4, ks=33), then separable blur with reflect-101
// ---------------------------------------------------------------------------
__global__ void kw_init_kernel() {
    float w[KS];
    float s = 0.f;
#pragma unroll
    for (int t = 0; t < KS; ++t) {
        float d = (float)(t - RR);
        w[t] = expf(-(d * d) / 32.0f);   // 2*sigma^2 = 32
        s += w[t];
    }
#pragma unroll
    for (int t = 0; t < KS; ++t) g_kw[t] = w[t] / s;
}

__device__ __forceinline__ int reflect101(int i) {
    i = (i < 0) ? -i : i;
    i = (i >= IMG) ? (2 * IMG - 2 - i) : i;
    return i;
}

__global__ void blur_h_kernel() {
    int idx = blockIdx.x * blockDim.x + threadIdx.x;
    if (idx >= BB * IMG * IMG) return;
    int x = idx % IMG;
    int rowbase = idx - x;
    float acc = 0.f;
#pragma unroll
    for (int t = 0; t < KS; ++t) {
        int xx = reflect101(x - RR + t);
        acc = fmaf(g_kw[t], g_mask[rowbase + xx], acc);
    }
    g_tmp[idx] = acc;
}

__global__ void blur_v_kernel(float* __restrict__ out_mask) {
    int idx = blockIdx.x * blockDim.x + threadIdx.x;
    if (idx >= BB * IMG * IMG) return;
    int x = idx % IMG;
    int y = (idx / IMG) % IMG;
    int b = idx / (IMG * IMG);
    float acc = 0.f;
#pragma unroll
    for (int t = 0; t < KS; ++t) {
        int yy = reflect101(y - RR + t);
        acc = fmaf(g_kw[t], g_tmp[(b * IMG + yy) * IMG + x], acc);
    }
    out_mask[idx] = acc;
}

// ---------------------------------------------------------------------------
// launch: out = [score(4) | mask(4*224*224)]
// ---------------------------------------------------------------------------
extern "C" void kernel_launch(void* const* d_in, const int* in_sizes, int n_in,
                              void* d_out, int out_size) {
    const float* x0 = (const float*)d_in[0];
    const float* x1 = (const float*)d_in[1];
    const float* x2 = (const float*)d_in[2];
    const float* f0 = (const float*)d_in[3];
    const float* f1 = (const float*)d_in[4];
    const float* f2 = (const float*)d_in[5];
    float* out = (float*)d_out;

    kw_init_kernel<<<1, 1>>>();
    dist_kernel<<<NN, 128>>>(x2, f2);
    topk_kernel<<<BB, 256>>>(out);                       // scores -> out[0..3]
    mindist_kernel<HW0, C0><<<dim3(HW0, BB), 256>>>(x0, f0);
    mindist_kernel<HW1, C1><<<dim3(HW1, BB), 256>>>(x1, f1);

    int total = BB * IMG * IMG;
    int blocks = (total + 255) / 256;
    resize_avg_kernel<<<blocks, 256>>>();
    blur_h_kernel<<<blocks, 256>>>();
    blur_v_kernel<<<blocks, 256>>>(out + BB);            // mask -> out[4..]
}

// round 5
// speedup vs baseline: 1.2730x; 1.2730x over previous
#include <cuda_runtime.h>
#include <math.h>

#define BB   4
#define NN   500
#define KNN  50
#define DD   2048
#define H0   28
#define HW0  (H0*H0)
#define C0   512
#define H1   14
#define HW1  (H1*H1)
#define C1   1024
#define IMG  224
#define KS   33
#define RR   16

// scratch (static device globals — no runtime allocation)
__device__ float g_dist[BB * NN];
__device__ int   g_idx[BB * KNN];
__device__ float g_m0[BB * HW0];
__device__ float g_m1[BB * HW1];
__device__ float g_tmp[BB * IMG * IMG];
__device__ float g_kw[KS];

// ---------------------------------------------------------------------------
// 1) pairwise distances q[4,2048] vs bank[500,2048] -> g_dist[4*500]
//    one block per n, one warp per b
// ---------------------------------------------------------------------------
__global__ void dist_kernel(const float* __restrict__ q,
                            const float* __restrict__ bank) {
    int n    = blockIdx.x;
    int lane = threadIdx.x & 31;
    int b    = threadIdx.x >> 5;

    const float4* qb = (const float4*)(q    + (size_t)b * DD);
    const float4* bk = (const float4*)(bank + (size_t)n * DD);

    float acc = 0.f;
#pragma unroll
    for (int j = 0; j < DD / 128; ++j) {
        float4 a = qb[lane + 32 * j];
        float4 c = bk[lane + 32 * j];
        float dx = a.x - c.x, dy = a.y - c.y, dz = a.z - c.z, dw = a.w - c.w;
        acc = fmaf(dx, dx, acc);
        acc = fmaf(dy, dy, acc);
        acc = fmaf(dz, dz, acc);
        acc = fmaf(dw, dw, acc);
    }
#pragma unroll
    for (int o = 16; o; o >>= 1) acc += __shfl_xor_sync(0xFFFFFFFFu, acc, o);
    if (lane == 0) g_dist[b * NN + n] = sqrtf(acc);
}

// ---------------------------------------------------------------------------
// 2) top-K smallest per b: single block, warp b handles batch b.
//    Each lane owns 16 of 500 values in registers; 50 shuffle-only argmin
//    rounds; ties break toward lower index (jax.lax.top_k behavior).
//    Zero __syncthreads.
// ---------------------------------------------------------------------------
__global__ void topk_kernel(float* __restrict__ out_score) {
    int b    = threadIdx.x >> 5;       // 4 warps
    int lane = threadIdx.x & 31;

    float v[16];
#pragma unroll
    for (int i = 0; i < 16; ++i) {
        int idx = lane + 32 * i;
        v[i] = (idx < NN) ? g_dist[b * NN + idx] : 3.4e38f;
    }

    float ssum = 0.f;
    for (int k = 0; k < KNN; ++k) {
        // local argmin over 16 register slots
        float best = 3.4e38f;
        int   bi   = 0x7FFFFFFF;
        int   bslot = -1;
#pragma unroll
        for (int i = 0; i < 16; ++i) {
            int idx = lane + 32 * i;
            if (v[i] < best || (v[i] == best && idx < bi)) {
                best = v[i]; bi = idx; bslot = i;
            }
        }
        // warp argmin (value, then lower index)
        float rbest = best;
        int   rbi   = bi;
#pragma unroll
        for (int o = 16; o; o >>= 1) {
            float v2 = __shfl_xor_sync(0xFFFFFFFFu, rbest, o);
            int   i2 = __shfl_xor_sync(0xFFFFFFFFu, rbi,   o);
            if (v2 < rbest || (v2 == rbest && i2 < rbi)) { rbest = v2; rbi = i2; }
        }
        // owning lane invalidates its slot
        if (bi == rbi) v[bslot] = 3.4e38f;
        if (lane == 0) g_idx[b * KNN + k] = rbi;
        ssum += rbest;
    }
    if (lane == 0) out_score[b] = ssum / (float)KNN;
}

// ---------------------------------------------------------------------------
// 3) per-pixel min distance over K gathered neighbors — BOTH levels fused.
//    blockIdx.x < HW0 -> level0 (C=512); else level1 (C=1024).
//    8 warps; each warp processes neighbor pairs (k, k+8) for double MLP.
// ---------------------------------------------------------------------------
template <int HW, int C>
__device__ __forceinline__ void mindist_body(const float* __restrict__ x,
                                             const float* __restrict__ f,
                                             int pos, int b,
                                             float* __restrict__ m) {
    constexpr int J = C / 128;
    int warp = threadIdx.x >> 5;
    int lane = threadIdx.x & 31;

    const float4* xr = (const float4*)(x + ((size_t)b * HW + pos) * C);
    float4 xv[J];
#pragma unroll
    for (int j = 0; j < J; ++j) xv[j] = xr[lane + 32 * j];

    float best = 3.4e38f;
    for (int k = warp; k < KNN; k += 16) {
        int k2 = k + 8;
        int n1 = g_idx[b * KNN + k];
        int n2 = (k2 < KNN) ? g_idx[b * KNN + k2] : n1;
        const float4* fr1 = (const float4*)(f + ((size_t)n1 * HW + pos) * C);
        const float4* fr2 = (const float4*)(f + ((size_t)n2 * HW + pos) * C);

        float a1 = 0.f, a2 = 0.f;
#pragma unroll
        for (int j = 0; j < J; ++j) {
            float4 c1 = fr1[lane + 32 * j];
            float4 c2 = fr2[lane + 32 * j];
            float d;
            d = xv[j].x - c1.x; a1 = fmaf(d, d, a1);
            d = xv[j].y - c1.y; a1 = fmaf(d, d, a1);
            d = xv[j].z - c1.z; a1 = fmaf(d, d, a1);
            d = xv[j].w - c1.w; a1 = fmaf(d, d, a1);
            d = xv[j].x - c2.x; a2 = fmaf(d, d, a2);
            d = xv[j].y - c2.y; a2 = fmaf(d, d, a2);
            d = xv[j].z - c2.z; a2 = fmaf(d, d, a2);
            d = xv[j].w - c2.w; a2 = fmaf(d, d, a2);
        }
#pragma unroll
        for (int o = 16; o; o >>= 1) {
            a1 += __shfl_xor_sync(0xFFFFFFFFu, a1, o);
            a2 += __shfl_xor_sync(0xFFFFFFFFu, a2, o);
        }
        best = fminf(best, a1);
        if (k2 < KNN) best = fminf(best, a2);
    }

    __shared__ float sb[8];
    if (lane == 0) sb[warp] = best;
    __syncthreads();
    if (threadIdx.x == 0) {
        float v = sb[0];
#pragma unroll
        for (int i = 1; i < 8; ++i) v = fminf(v, sb[i]);
        m[b * HW + pos] = sqrtf(v);
    }
}

__global__ void __launch_bounds__(256) mindist_all_kernel(
        const float* __restrict__ x0, const float* __restrict__ f0,
        const float* __restrict__ x1, const float* __restrict__ f1) {
    int b = blockIdx.y;
    if (blockIdx.x < HW0) {
        mindist_body<HW0, C0>(x0, f0, blockIdx.x, b, g_m0);
    } else {
        mindist_body<HW1, C1>(x1, f1, blockIdx.x - HW0, b, g_m1);
    }
}

// ---------------------------------------------------------------------------
// 4) bilinear upsample (half-pixel centers, edge clamp), average, and
//    horizontal blur — fused. One block per (b, y) output row; the 224 mask
//    values of the row are built in smem, then each thread does the 33-tap
//    horizontal pass over smem.
// ---------------------------------------------------------------------------
__device__ __forceinline__ float bilerp(const float* __restrict__ img, int S,
                                        float cx, float cy) {
    float fx = floorf(cx), fy = floorf(cy);
    int x0 = (int)fx, y0 = (int)fy;
    float wx = cx - fx, wy = cy - fy;
    int x1 = min(x0 + 1, S - 1), y1 = min(y0 + 1, S - 1);
    x0 = max(x0, 0); y0 = max(y0, 0);
    float v00 = img[y0 * S + x0], v01 = img[y0 * S + x1];
    float v10 = img[y1 * S + x0], v11 = img[y1 * S + x1];
    return (1.f - wy) * ((1.f - wx) * v00 + wx * v01)
         + wy * ((1.f - wx) * v10 + wx * v11);
}

__device__ __forceinline__ int reflect101(int i) {
    i = (i < 0) ? -i : i;
    i = (i >= IMG) ? (2 * IMG - 2 - i) : i;
    return i;
}

__global__ void __launch_bounds__(IMG) resize_blurh_kernel() {
    int b = blockIdx.y;
    int y = blockIdx.x;
    int x = threadIdx.x;

    __shared__ float row[IMG];

    float cx0 = (x + 0.5f) * ((float)H0 / IMG) - 0.5f;
    float cy0 = (y + 0.5f) * ((float)H0 / IMG) - 0.5f;
    float cx1 = (x + 0.5f) * ((float)H1 / IMG) - 0.5f;
    float cy1 = (y + 0.5f) * ((float)H1 / IMG) - 0.5f;

    float m0 = bilerp(g_m0 + b * HW0, H0, cx0, cy0);
    float m1 = bilerp(g_m1 + b * HW1, H1, cx1, cy1);
    row[x] = 0.5f * (m0 + m1);
    __syncthreads();

    float acc = 0.f;
#pragma unroll
    for (int t = 0; t < KS; ++t) {
        int xx = reflect101(x - RR + t);
        acc = fmaf(g_kw[t], row[xx], acc);
    }
    g_tmp[(b * IMG + y) * IMG + x] = acc;
}

__global__ void __launch_bounds__(IMG) blur_v_kernel(float* __restrict__ out_mask) {
    int b = blockIdx.y;
    int y = blockIdx.x;
    int x = threadIdx.x;
    float acc = 0.f;
#pragma unroll
    for (int t = 0; t < KS; ++t) {
        int yy = reflect101(y - RR + t);
        acc = fmaf(g_kw[t], g_tmp[(b * IMG + yy) * IMG + x], acc);
    }
    out_mask[(b * IMG + y) * IMG + x] = acc;
}

// ---------------------------------------------------------------------------
// 5) gaussian weights (sigma=4, ks=33)
// ---------------------------------------------------------------------------
__global__ void kw_init_kernel() {
    float w[KS];
    float s = 0.f;
#pragma unroll
    for (int t = 0; t < KS; ++t) {
        float d = (float)(t - RR);
        w[t] = expf(-(d * d) / 32.0f);   // 2*sigma^2 = 32
        s += w[t];
    }
#pragma unroll
    for (int t = 0; t < KS; ++t) g_kw[t] = w[t] / s;
}

// ---------------------------------------------------------------------------
// launch: out = [score(4) | mask(4*224*224)]
// ---------------------------------------------------------------------------
extern "C" void kernel_launch(void* const* d_in, const int* in_sizes, int n_in,
                              void* d_out, int out_size) {
    const float* x0 = (const float*)d_in[0];
    const float* x1 = (const float*)d_in[1];
    const float* x2 = (const float*)d_in[2];
    const float* f0 = (const float*)d_in[3];
    const float* f1 = (const float*)d_in[4];
    const float* f2 = (const float*)d_in[5];
    float* out = (float*)d_out;

    kw_init_kernel<<<1, 1>>>();
    dist_kernel<<<NN, 128>>>(x2, f2);
    topk_kernel<<<1, 128>>>(out);                        // scores -> out[0..3]
    mindist_all_kernel<<<dim3(HW0 + HW1, BB), 256>>>(x0, f0, x1, f1);
    resize_blurh_kernel<<<dim3(IMG, BB), IMG>>>();
    blur_v_kernel<<<dim3(IMG, BB), IMG>>>(out + BB);     // mask -> out[4..]
}

// round 9
// speedup vs baseline: 1.3940x; 1.0950x over previous
#include <cuda_runtime.h>
#include <math.h>

#define BB   4
#define NN   500
#define KNN  50
#define DD   2048
#define H0   28
#define HW0  (H0*H0)
#define C0   512
#define H1   14
#define HW1  (H1*H1)
#define C1   1024
#define IMG  224
#define KS   33
#define RR   16

// scratch (static device globals — no runtime allocation)
__device__ float g_dist[BB * NN];
__device__ int   g_idx[BB * KNN];
__device__ float g_m0[BB * HW0];
__device__ float g_m1[BB * HW1];
__device__ float g_tmp[BB * IMG * IMG];
__device__ float g_kw[KS];

// ---------------------------------------------------------------------------
// 1) pairwise distances q[4,2048] vs bank[500,2048] -> g_dist[4*500]
//    one block per n, one warp per b
// ---------------------------------------------------------------------------
__global__ void dist_kernel(const float* __restrict__ q,
                            const float* __restrict__ bank) {
    int n    = blockIdx.x;
    int lane = threadIdx.x & 31;
    int b    = threadIdx.x >> 5;

    const float4* qb = (const float4*)(q    + (size_t)b * DD);
    const float4* bk = (const float4*)(bank + (size_t)n * DD);

    float acc = 0.f;
#pragma unroll
    for (int j = 0; j < DD / 128; ++j) {
        float4 a = qb[lane + 32 * j];
        float4 c = bk[lane + 32 * j];
        float dx = a.x - c.x, dy = a.y - c.y, dz = a.z - c.z, dw = a.w - c.w;
        acc = fmaf(dx, dx, acc);
        acc = fmaf(dy, dy, acc);
        acc = fmaf(dz, dz, acc);
        acc = fmaf(dw, dw, acc);
    }
#pragma unroll
    for (int o = 16; o; o >>= 1) acc += __shfl_xor_sync(0xFFFFFFFFu, acc, o);
    if (lane == 0) g_dist[b * NN + n] = sqrtf(acc);
}

// ---------------------------------------------------------------------------
// 2) top-K smallest per b: single block, warp b handles batch b.
//    Register-resident shuffle-only argmin, ties toward lower index.
//    Thread 0 also computes the gaussian weights (replaces kw_init launch).
// ---------------------------------------------------------------------------
__global__ void topk_kernel(float* __restrict__ out_score) {
    if (threadIdx.x == 0) {
        float w[KS];
        float s = 0.f;
#pragma unroll
        for (int t = 0; t < KS; ++t) {
            float d = (float)(t - RR);
            w[t] = expf(-(d * d) / 32.0f);   // 2*sigma^2 = 32
            s += w[t];
        }
#pragma unroll
        for (int t = 0; t < KS; ++t) g_kw[t] = w[t] / s;
    }

    int b    = threadIdx.x >> 5;       // 4 warps
    int lane = threadIdx.x & 31;

    float v[16];
#pragma unroll
    for (int i = 0; i < 16; ++i) {
        int idx = lane + 32 * i;
        v[i] = (idx < NN) ? g_dist[b * NN + idx] : 3.4e38f;
    }

    float ssum = 0.f;
    for (int k = 0; k < KNN; ++k) {
        float best = 3.4e38f;
        int   bi   = 0x7FFFFFFF;
        int   bslot = -1;
#pragma unroll
        for (int i = 0; i < 16; ++i) {
            int idx = lane + 32 * i;
            if (v[i] < best || (v[i] == best && idx < bi)) {
                best = v[i]; bi = idx; bslot = i;
            }
        }
        float rbest = best;
        int   rbi   = bi;
#pragma unroll
        for (int o = 16; o; o >>= 1) {
            float v2 = __shfl_xor_sync(0xFFFFFFFFu, rbest, o);
            int   i2 = __shfl_xor_sync(0xFFFFFFFFu, rbi,   o);
            if (v2 < rbest || (v2 == rbest && i2 < rbi)) { rbest = v2; rbi = i2; }
        }
        if (bi == rbi) v[bslot] = 3.4e38f;
        if (lane == 0) g_idx[b * KNN + k] = rbi;
        ssum += rbest;
    }
    if (lane == 0) out_score[b] = ssum / (float)KNN;
}

// ---------------------------------------------------------------------------
// 3) per-pixel min distance over K gathered neighbors — BOTH levels fused.
//    grid = (BB, HW0+HW1): the 4 batch-blocks of one pos are ADJACENT, so
//    shared neighbor rows across batches hit L2 instead of DRAM.
//    x row lives in smem (not registers) -> low regs -> high occupancy.
//    8 warps; each warp processes neighbor pairs (k, k+8) for double MLP.
// ---------------------------------------------------------------------------
template <int HW, int C>
__device__ __forceinline__ void mindist_body(const float* __restrict__ x,
                                             const float* __restrict__ f,
                                             int pos, int b,
                                             float* __restrict__ m,
                                             float4* __restrict__ xs) {
    constexpr int J = C / 128;
    int warp = threadIdx.x >> 5;
    int lane = threadIdx.x & 31;

    const float4* xr = (const float4*)(x + ((size_t)b * HW + pos) * C);
    for (int i = threadIdx.x; i < C / 4; i += 256) xs[i] = xr[i];
    __syncthreads();

    float best = 3.4e38f;
    for (int k = warp; k < KNN; k += 16) {
        int k2 = k + 8;
        int n1 = g_idx[b * KNN + k];
        int n2 = (k2 < KNN) ? g_idx[b * KNN + k2] : n1;
        const float4* fr1 = (const float4*)(f + ((size_t)n1 * HW + pos) * C);
        const float4* fr2 = (const float4*)(f + ((size_t)n2 * HW + pos) * C);

        float a1 = 0.f, a2 = 0.f;
#pragma unroll
        for (int j = 0; j < J; ++j) {
            float4 c1 = fr1[lane + 32 * j];
            float4 c2 = fr2[lane + 32 * j];
            float4 xv = xs[lane + 32 * j];
            float d;
            d = xv.x - c1.x; a1 = fmaf(d, d, a1);
            d = xv.y - c1.y; a1 = fmaf(d, d, a1);
            d = xv.z - c1.z; a1 = fmaf(d, d, a1);
            d = xv.w - c1.w; a1 = fmaf(d, d, a1);
            d = xv.x - c2.x; a2 = fmaf(d, d, a2);
            d = xv.y - c2.y; a2 = fmaf(d, d, a2);
            d = xv.z - c2.z; a2 = fmaf(d, d, a2);
            d = xv.w - c2.w; a2 = fmaf(d, d, a2);
        }
#pragma unroll
        for (int o = 16; o; o >>= 1) {
            a1 += __shfl_xor_sync(0xFFFFFFFFu, a1, o);
            a2 += __shfl_xor_sync(0xFFFFFFFFu, a2, o);
        }
        best = fminf(best, a1);
        if (k2 < KNN) best = fminf(best, a2);
    }

    __shared__ float sb[8];
    if (lane == 0) sb[warp] = best;
    __syncthreads();
    if (threadIdx.x == 0) {
        float v = sb[0];
#pragma unroll
        for (int i = 1; i < 8; ++i) v = fminf(v, sb[i]);
        m[b * HW + pos] = sqrtf(v);
    }
}

__global__ void __launch_bounds__(256) mindist_all_kernel(
        const float* __restrict__ x0, const float* __restrict__ f0,
        const float* __restrict__ x1, const float* __restrict__ f1) {
    __shared__ float4 xs[C1 / 4];       // 4KB, covers both levels
    int b = blockIdx.x;
    int q = blockIdx.y;
    if (q < HW0) {
        mindist_body<HW0, C0>(x0, f0, q, b, g_m0, xs);
    } else {
        mindist_body<HW1, C1>(x1, f1, q - HW0, b, g_m1, xs);
    }
}

// ---------------------------------------------------------------------------
// 4) bilinear upsample (half-pixel centers, edge clamp), average, and
//    horizontal blur — fused per output row.
// ---------------------------------------------------------------------------
__device__ __forceinline__ float bilerp(const float* __restrict__ img, int S,
                                        float cx, float cy) {
    float fx = floorf(cx), fy = floorf(cy);
    int x0 = (int)fx, y0 = (int)fy;
    float wx = cx - fx, wy = cy - fy;
    int x1 = min(x0 + 1, S - 1), y1 = min(y0 + 1, S - 1);
    x0 = max(x0, 0); y0 = max(y0, 0);
    float v00 = img[y0 * S + x0], v01 = img[y0 * S + x1];
    float v10 = img[y1 * S + x0], v11 = img[y1 * S + x1];
    return (1.f - wy) * ((1.f - wx) * v00 + wx * v01)
         + wy * ((1.f - wx) * v10 + wx * v11);
}

__device__ __forceinline__ int reflect101(int i) {
    i = (i < 0) ? -i : i;
    i = (i >= IMG) ? (2 * IMG - 2 - i) : i;
    return i;
}

__global__ void __launch_bounds__(IMG) resize_blurh_kernel() {
    int b = blockIdx.y;
    int y = blockIdx.x;
    int x = threadIdx.x;

    __shared__ float row[IMG];

    float cx0 = (x + 0.5f) * ((float)H0 / IMG) - 0.5f;
    float cy0 = (y + 0.5f) * ((float)H0 / IMG) - 0.5f;
    float cx1 = (x + 0.5f) * ((float)H1 / IMG) - 0.5f;
    float cy1 = (y + 0.5f) * ((float)H1 / IMG) - 0.5f;

    float m0 = bilerp(g_m0 + b * HW0, H0, cx0, cy0);
    float m1 = bilerp(g_m1 + b * HW1, H1, cx1, cy1);
    row[x] = 0.5f * (m0 + m1);
    __syncthreads();

    float acc = 0.f;
#pragma unroll
    for (int t = 0; t < KS; ++t) {
        int xx = reflect101(x - RR + t);
        acc = fmaf(g_kw[t], row[xx], acc);
    }
    g_tmp[(b * IMG + y) * IMG + x] = acc;
}

__global__ void __launch_bounds__(IMG) blur_v_kernel(float* __restrict__ out_mask) {
    int b = blockIdx.y;
    int y = blockIdx.x;
    int x = threadIdx.x;
    float acc = 0.f;
#pragma unroll
    for (int t = 0; t < KS; ++t) {
        int yy = reflect101(y - RR + t);
        acc = fmaf(g_kw[t], g_tmp[(b * IMG + yy) * IMG + x], acc);
    }
    out_mask[(b * IMG + y) * IMG + x] = acc;
}

// ---------------------------------------------------------------------------
// launch: out = [score(4) | mask(4*224*224)]
// ---------------------------------------------------------------------------
extern "C" void kernel_launch(void* const* d_in, const int* in_sizes, int n_in,
                              void* d_out, int out_size) {
    const float* x0 = (const float*)d_in[0];
    const float* x1 = (const float*)d_in[1];
    const float* x2 = (const float*)d_in[2];
    const float* f0 = (const float*)d_in[3];
    const float* f1 = (const float*)d_in[4];
    const float* f2 = (const float*)d_in[5];
    float* out = (float*)d_out;

    dist_kernel<<<NN, 128>>>(x2, f2);
    topk_kernel<<<1, 128>>>(out);                        // scores + gaussian kw
    mindist_all_kernel<<<dim3(BB, HW0 + HW1), 256>>>(x0, f0, x1, f1);
    resize_blurh_kernel<<<dim3(IMG, BB), IMG>>>();
    blur_v_kernel<<<dim3(IMG, BB), IMG>>>(out + BB);     // mask -> out[4..]
}